// round 2
// baseline (speedup 1.0000x reference)
#include <cuda_runtime.h>
#include <cuda_bf16.h>

#define Bb 8
#define Nn 96
#define Dd 256
#define Hh 8
#define CUTOFF 5.0f
#define PI_F 3.14159265358979f

// ---------------- scratch (device globals; no allocation allowed) ----------------
__device__ float gQ[Bb*Nn*Dd];
__device__ float gK[Bb*Nn*Dd];
__device__ float gV[Bb*Nn*Dd];
__device__ float gDU[Bb*Nn*3*Dd];
__device__ float gWS[Bb*Nn*3*Dd];
__device__ float gWT[Bb*Nn*3*Dd];
__device__ unsigned char gMask[Bb*Nn*Nn];

// ---------------- mask dtype canonicalization ----------------
// key_padding_mask is a jnp bool; the harness materializes it as an unknown
// physical dtype (uint8 / int32 / float32). Detect from byte patterns and
// canonicalize into gMask (1 byte per element, 0/1).
//  - uint8 storage: nonzero bytes (==1, or 0xFF) appear at indices i%4 != 0
//  - float32 storage: bytes 0x80 / 0x3F appear at i%4 == 2/3
//  - int32 storage: nonzero bytes ONLY at i%4 == 0
__global__ void mask_conv_kernel(const unsigned char* __restrict__ raw) {
    __shared__ int mode_s;
    int tid = threadIdx.x;
    if (tid == 0) mode_s = 0;
    __syncthreads();
    int local = 0;
    const int NEL = Bb*Nn*Nn;
    for (int i = tid; i < NEL; i += 256) {
        unsigned char bch = raw[i];
        if (bch != 0 && (i & 3) != 0) {
            if (bch == 0x80 || bch == 0x3F) local |= 2;   // float32 pattern
            else                            local |= 1;   // byte-per-element
        }
    }
    if (local) atomicOr(&mode_s, local);
    __syncthreads();
    int mode = mode_s;
    for (int i = tid; i < NEL; i += 256) {
        unsigned char v;
        if (mode & 1)      v = (raw[i] != 0);
        else if (mode & 2) v = (((const float*)raw)[i] != 0.0f);
        else               v = (((const int*)raw)[i]   != 0);
        gMask[i] = v;
    }
}

// ---------------- FMA-only silu (avoids MUFU bottleneck: ~44M silus in this problem)
__device__ __forceinline__ float fast_silu(float x) {
    float t = x * -1.4426950408889634f;          // -x * log2(e)
    t = fminf(fmaxf(t, -30.0f), 30.0f);
    float fn = rintf(t);
    float f  = t - fn;                            // f in [-0.5, 0.5]
    float p = 1.3333558e-3f;
    p = fmaf(p, f, 9.6181291e-3f);
    p = fmaf(p, f, 5.5504109e-2f);
    p = fmaf(p, f, 2.4022651e-1f);
    p = fmaf(p, f, 6.9314718e-1f);
    p = fmaf(p, f, 1.0f);
    int ei = (int)fn;
    float sc = __int_as_float((ei + 127) << 23);
    float e = p * sc;                             // ~= exp(-x)
    float d = 1.0f + e;
    float y = __int_as_float(0x7EF311C3u - __float_as_int(d));
    y = y * (2.0f - d * y);
    y = y * (2.0f - d * y);
    y = y * (2.0f - d * y);
    return x * y;
}

// ---------------- K0: Q/K/V = x @ W + b  (small) ----------------
__global__ __launch_bounds__(256) void qkv_kernel(
    const float* __restrict__ x,
    const float* __restrict__ Wq, const float* __restrict__ bq,
    const float* __restrict__ Wk, const float* __restrict__ bk,
    const float* __restrict__ Wv, const float* __restrict__ bv)
{
    __shared__ float xs[12][256];
    __shared__ float wch[32][256];
    int tid = threadIdx.x;
    int b   = blockIdx.x >> 3;
    int rg  = blockIdx.x & 7;
    int row0 = rg * 12;

    #pragma unroll
    for (int i = 0; i < 12; ++i)
        xs[i][tid] = x[(b*Nn + row0 + i)*Dd + tid];

    const float* Ws[3]  = {Wq, Wk, Wv};
    const float* bs[3]  = {bq, bk, bv};
    float*       os[3]  = {gQ, gK, gV};

    for (int w = 0; w < 3; ++w) {
        float acc[12];
        #pragma unroll
        for (int i = 0; i < 12; ++i) acc[i] = 0.f;
        const float* W = Ws[w];
        for (int ks = 0; ks < 8; ++ks) {
            __syncthreads();
            #pragma unroll
            for (int i = 0; i < 32; ++i)
                wch[i][tid] = W[(ks*32 + i)*Dd + tid];
            __syncthreads();
            #pragma unroll
            for (int kk = 0; kk < 32; kk += 4) {
                float w0 = wch[kk+0][tid], w1 = wch[kk+1][tid];
                float w2 = wch[kk+2][tid], w3 = wch[kk+3][tid];
                #pragma unroll
                for (int r = 0; r < 12; ++r) {
                    float4 xv = *(const float4*)&xs[r][ks*32 + kk];
                    acc[r] = fmaf(xv.x, w0, acc[r]);
                    acc[r] = fmaf(xv.y, w1, acc[r]);
                    acc[r] = fmaf(xv.z, w2, acc[r]);
                    acc[r] = fmaf(xv.w, w3, acc[r]);
                }
            }
        }
        float bias = bs[w][tid];
        #pragma unroll
        for (int r = 0; r < 12; ++r)
            os[w][(b*Nn + row0 + r)*Dd + tid] = acc[r] + bias;
        __syncthreads();
    }
}

// ---------------- shared GEMM tile: out[96][128-chunk] = src(96x256 smem) @ W[:,cc:cc+128]
__device__ __forceinline__ void gemm_tile(
    const float* __restrict__ src,   // smem [96][256]
    const float* __restrict__ Wglob, // global [256][256]
    int cc, float* wch, int g, int r, int tid, float acc[12][4])
{
    for (int ks = 0; ks < 8; ++ks) {
        __syncthreads();
        {
            const float* Wp = Wglob + (ks*32)*Dd + cc;
            float4* w4 = (float4*)wch;
            #pragma unroll
            for (int i = 0; i < 4; ++i) {
                int lin = tid + 256*i;          // 0..1023 float4s = 32x128 floats
                int row = lin >> 5;
                int c4  = lin & 31;
                w4[lin] = *(const float4*)(Wp + row*Dd + c4*4);
            }
        }
        __syncthreads();
        #pragma unroll
        for (int kk = 0; kk < 32; kk += 4) {
            float4 w0 = *(const float4*)&wch[(kk+0)*128 + g*4];
            float4 w1 = *(const float4*)&wch[(kk+1)*128 + g*4];
            float4 w2 = *(const float4*)&wch[(kk+2)*128 + g*4];
            float4 w3 = *(const float4*)&wch[(kk+3)*128 + g*4];
            #pragma unroll
            for (int i = 0; i < 12; ++i) {
                float4 e = *(const float4*)&src[(r + (i<<3))*Dd + ks*32 + kk];
                acc[i][0] = fmaf(e.x, w0.x, fmaf(e.y, w1.x, fmaf(e.z, w2.x, fmaf(e.w, w3.x, acc[i][0]))));
                acc[i][1] = fmaf(e.x, w0.y, fmaf(e.y, w1.y, fmaf(e.z, w2.y, fmaf(e.w, w3.y, acc[i][1]))));
                acc[i][2] = fmaf(e.x, w0.z, fmaf(e.y, w1.z, fmaf(e.z, w2.z, fmaf(e.w, w3.z, acc[i][2]))));
                acc[i][3] = fmaf(e.x, w0.w, fmaf(e.y, w1.w, fmaf(e.z, w2.w, fmaf(e.w, w3.w, acc[i][3]))));
            }
        }
    }
}

// ---------------- K1: fused dk-GEMM + attention + attn_per_nodes + du-GEMM ----------------
#define FUSED_SMEM_FLOATS (24576 + 24576 + 4096 + 256 + 96 + 96 + 288 + 256 + 768)

__global__ __launch_bounds__(256, 1) void fused_kernel(
    const float* __restrict__ edge,
    const float* __restrict__ dist,
    const float* __restrict__ vec,
    const float* __restrict__ Wdk, const float* __restrict__ bdk,
    const float* __restrict__ Wdu, const float* __restrict__ bdu,
    float* __restrict__ out_attn)
{
    extern __shared__ float sm[];
    float* Es     = sm;                 // 96x256 edge tile
    float* As     = Es + 24576;         // 96x256 attn_per_nodes
    float* wch    = As + 24576;         // 32x128 weight slice
    float* qs     = wch + 4096;         // 256
    float* scl    = qs + 256;           // 96  (mask-folded cosine scale)
    float* mk     = scl + 96;           // 96  (du keep factor)
    float* vecs   = mk + 96;            // 96x3
    float* bias_s = vecs + 288;         // 256 (bdk then bdu)
    float* du_s   = bias_s + 256;       // 3x256

    int tid = threadIdx.x;
    int b = blockIdx.x / Nn;
    int n = blockIdx.x % Nn;
    int g = tid & 31;
    int r = tid >> 5;
    size_t ebase = (size_t)(b*Nn + n) * Nn * Dd;

    // ------- loads -------
    {
        const float4* e4  = (const float4*)(edge + ebase);
        float4*       Es4 = (float4*)Es;
        #pragma unroll
        for (int i = 0; i < 24; ++i) Es4[tid + 256*i] = e4[tid + 256*i];
    }
    qs[tid]     = gQ[(b*Nn + n)*Dd + tid];
    bias_s[tid] = bdk[tid];
    if (tid < 96) {
        int m = tid;
        unsigned char mm = gMask[(b*Nn + n)*Nn + m];
        float dd = dist[(b*Nn + n)*Nn + m];
        float cs = (dd < CUTOFF) ? 0.5f*(cosf(dd*(PI_F/CUTOFF)) + 1.f) : 0.f;
        scl[m] = mm ? 0.f : cs;
        mk[m]  = mm ? 0.f : 1.f;
    }
    {
        size_t vbase = (size_t)(b*Nn + n) * Nn * 3;
        vecs[tid] = vec[vbase + tid];
        if (tid < 32) vecs[256 + tid] = vec[vbase + 256 + tid];
    }
    du_s[tid] = 0.f; du_s[tid+256] = 0.f; du_s[tid+512] = 0.f;
    __syncthreads();

    // ------- GEMM1: dk = silu(E @ Wdk + bdk); attn weights; attn_per_nodes -> As -------
    #pragma unroll 1
    for (int cc = 0; cc < 256; cc += 128) {
        float acc[12][4];
        #pragma unroll
        for (int i = 0; i < 12; ++i) { acc[i][0]=0.f; acc[i][1]=0.f; acc[i][2]=0.f; acc[i][3]=0.f; }
        gemm_tile(Es, Wdk, cc, wch, g, r, tid, acc);

        int col0 = cc + g*4;
        float4 qv = *(const float4*)&qs[col0];
        float4 bb = *(const float4*)&bias_s[col0];
        #pragma unroll
        for (int i = 0; i < 12; ++i) {
            int m = r + (i << 3);
            float4 kv = *(const float4*)&gK[(b*Nn + m)*Dd + col0];
            float p;
            p  = fast_silu(acc[i][0] + bb.x) * qv.x * kv.x;
            p += fast_silu(acc[i][1] + bb.y) * qv.y * kv.y;
            p += fast_silu(acc[i][2] + bb.z) * qv.z * kv.z;
            p += fast_silu(acc[i][3] + bb.w) * qv.w * kv.w;
            // reduce 32 head-dims: each head owns 8 adjacent lanes (4 cols each)
            p += __shfl_xor_sync(0xffffffffu, p, 1);
            p += __shfl_xor_sync(0xffffffffu, p, 2);
            p += __shfl_xor_sync(0xffffffffu, p, 4);
            float prob = fast_silu(p) * scl[m];
            float4 vv = *(const float4*)&gV[(b*Nn + m)*Dd + col0];
            float4 a;
            a.x = prob*vv.x; a.y = prob*vv.y; a.z = prob*vv.z; a.w = prob*vv.w;
            *(float4*)&As[m*Dd + col0] = a;
        }
    }
    __syncthreads();

    // ------- attn = sum_m As[m][:]; swap bias to bdu -------
    {
        float s = 0.f;
        #pragma unroll
        for (int m = 0; m < 96; ++m) s += As[m*Dd + tid];
        out_attn[(b*Nn + n)*Dd + tid] = s;
        bias_s[tid] = bdu[tid];
    }

    // ------- GEMM2: du_in = As @ Wdu + bdu (masked); du[c][:] += du_in * vec -------
    #pragma unroll 1
    for (int cc = 0; cc < 256; cc += 128) {
        float acc[12][4];
        #pragma unroll
        for (int i = 0; i < 12; ++i) { acc[i][0]=0.f; acc[i][1]=0.f; acc[i][2]=0.f; acc[i][3]=0.f; }
        gemm_tile(As, Wdu, cc, wch, g, r, tid, acc);

        int col0 = cc + g*4;
        float4 bb = *(const float4*)&bias_s[col0];
        float bbv[4] = {bb.x, bb.y, bb.z, bb.w};
        float dup0[4] = {0,0,0,0}, dup1[4] = {0,0,0,0}, dup2[4] = {0,0,0,0};
        #pragma unroll
        for (int i = 0; i < 12; ++i) {
            int m = r + (i << 3);
            float keep = mk[m];
            float vc0 = vecs[m*3+0], vc1 = vecs[m*3+1], vc2 = vecs[m*3+2];
            #pragma unroll
            for (int j = 0; j < 4; ++j) {
                float din = (acc[i][j] + bbv[j]) * keep;
                dup0[j] = fmaf(din, vc0, dup0[j]);
                dup1[j] = fmaf(din, vc1, dup1[j]);
                dup2[j] = fmaf(din, vc2, dup2[j]);
            }
        }
        #pragma unroll
        for (int j = 0; j < 4; ++j) {
            atomicAdd(&du_s[0*Dd + col0 + j], dup0[j]);
            atomicAdd(&du_s[1*Dd + col0 + j], dup1[j]);
            atomicAdd(&du_s[2*Dd + col0 + j], dup2[j]);
        }
    }
    __syncthreads();

    #pragma unroll
    for (int c = 0; c < 3; ++c)
        gDU[((b*Nn + n)*3 + c)*Dd + tid] = du_s[c*Dd + tid];
}

// ---------------- K2: w = du @ Wdih; split into ws / wt ----------------
__global__ __launch_bounds__(256) void w_kernel(const float* __restrict__ Wdih)
{
    __shared__ float dus[12*256];     // 4 n x 3 c x 256
    __shared__ float wch[16][512];
    int tid = threadIdx.x;
    int b  = blockIdx.x / 24;
    int ng = blockIdx.x % 24;
    int nbase = ng * 4;

    size_t dbase = (size_t)(b*Nn + nbase) * 3 * Dd;
    #pragma unroll
    for (int i = 0; i < 12; ++i)
        dus[tid + 256*i] = gDU[dbase + tid + 256*i];

    float acc0[12], acc1[12];
    #pragma unroll
    for (int q = 0; q < 12; ++q) { acc0[q] = 0.f; acc1[q] = 0.f; }

    for (int ks = 0; ks < 16; ++ks) {
        __syncthreads();
        #pragma unroll
        for (int i = 0; i < 32; ++i) {
            int lin = tid + 256*i;
            int row = lin >> 9;
            int col = lin & 511;
            wch[row][col] = Wdih[(ks*16 + row)*512 + col];
        }
        __syncthreads();
        #pragma unroll
        for (int kk = 0; kk < 16; ++kk) {
            float w0 = wch[kk][tid];
            float w1 = wch[kk][tid + 256];
            #pragma unroll
            for (int q = 0; q < 12; ++q) {
                float xv = dus[q*256 + ks*16 + kk];
                acc0[q] = fmaf(xv, w0, acc0[q]);
                acc1[q] = fmaf(xv, w1, acc1[q]);
            }
        }
    }
    #pragma unroll
    for (int q = 0; q < 12; ++q) {
        int ni = q / 3, c = q % 3;
        gWS[((b*Nn + nbase + ni)*3 + c)*Dd + tid] = acc0[q];
        gWT[((b*Nn + nbase + ni)*3 + c)*Dd + tid] = acc1[q];
    }
}

// ---------------- K3: ipe = silu(E @ Wea + bea) * sum_c ws[n,c,:]*wt[m,c,:] ----------------
#define IPE_SMEM_FLOATS (24576 + 4096 + 768 + 256)

__global__ __launch_bounds__(256, 1) void ipe_kernel(
    const float* __restrict__ edge,
    const float* __restrict__ Wea, const float* __restrict__ bea,
    float* __restrict__ out_ipe)
{
    extern __shared__ float sm[];
    float* Es    = sm;            // 96x256
    float* wch   = Es + 24576;    // 32x128
    float* wsr   = wch + 4096;    // 3x256
    float* bea_s = wsr + 768;     // 256

    int tid = threadIdx.x;
    int b = blockIdx.x / Nn;
    int n = blockIdx.x % Nn;
    int g = tid & 31;
    int r = tid >> 5;
    size_t ebase = (size_t)(b*Nn + n) * Nn * Dd;

    {
        const float4* e4  = (const float4*)(edge + ebase);
        float4*       Es4 = (float4*)Es;
        #pragma unroll
        for (int i = 0; i < 24; ++i) Es4[tid + 256*i] = e4[tid + 256*i];
    }
    bea_s[tid] = bea[tid];
    {
        size_t wbase = (size_t)(b*Nn + n) * 3 * Dd;
        #pragma unroll
        for (int i = 0; i < 3; ++i) wsr[tid + 256*i] = gWS[wbase + tid + 256*i];
    }
    __syncthreads();

    #pragma unroll 1
    for (int cc = 0; cc < 256; cc += 128) {
        float acc[12][4];
        #pragma unroll
        for (int i = 0; i < 12; ++i) { acc[i][0]=0.f; acc[i][1]=0.f; acc[i][2]=0.f; acc[i][3]=0.f; }
        gemm_tile(Es, Wea, cc, wch, g, r, tid, acc);

        int col0 = cc + g*4;
        float4 bb = *(const float4*)&bea_s[col0];
        float4 w0 = *(const float4*)&wsr[0*Dd + col0];
        float4 w1 = *(const float4*)&wsr[1*Dd + col0];
        float4 w2 = *(const float4*)&wsr[2*Dd + col0];
        #pragma unroll
        for (int i = 0; i < 12; ++i) {
            int m = r + (i << 3);
            const float* wtb = &gWT[((b*Nn + m)*3)*Dd + col0];
            float4 t0 = *(const float4*)(wtb);
            float4 t1 = *(const float4*)(wtb + 256);
            float4 t2 = *(const float4*)(wtb + 512);
            float4 o;
            o.x = fast_silu(acc[i][0] + bb.x) * (w0.x*t0.x + w1.x*t1.x + w2.x*t2.x);
            o.y = fast_silu(acc[i][1] + bb.y) * (w0.y*t0.y + w1.y*t1.y + w2.y*t2.y);
            o.z = fast_silu(acc[i][2] + bb.z) * (w0.z*t0.z + w1.z*t1.z + w2.z*t2.z);
            o.w = fast_silu(acc[i][3] + bb.w) * (w0.w*t0.w + w1.w*t1.w + w2.w*t2.w);
            *(float4*)&out_ipe[((size_t)(b*Nn + n)*Nn + m)*Dd + col0] = o;
        }
    }
}

// ---------------- launch ----------------
extern "C" void kernel_launch(void* const* d_in, const int* in_sizes, int n_in,
                              void* d_out, int out_size)
{
    const float* x    = (const float*)d_in[0];
    const float* vec  = (const float*)d_in[1];
    const float* dist = (const float*)d_in[2];
    const float* edge = (const float*)d_in[3];
    const unsigned char* mraw = (const unsigned char*)d_in[4];
    const float* Wq   = (const float*)d_in[5];
    const float* bq   = (const float*)d_in[6];
    const float* Wk   = (const float*)d_in[7];
    const float* bk   = (const float*)d_in[8];
    const float* Wv   = (const float*)d_in[9];
    const float* bv   = (const float*)d_in[10];
    const float* Wdk  = (const float*)d_in[11];
    const float* bdk  = (const float*)d_in[12];
    const float* Wdu  = (const float*)d_in[13];
    const float* bdu  = (const float*)d_in[14];
    const float* Wdih = (const float*)d_in[15];
    const float* Wea  = (const float*)d_in[16];
    const float* bea  = (const float*)d_in[17];

    float* out_attn = (float*)d_out;                    // (B,N,D)
    float* out_ipe  = out_attn + Bb*Nn*Dd;              // (B,N,N,D)

    cudaFuncSetAttribute(fused_kernel, cudaFuncAttributeMaxDynamicSharedMemorySize,
                         FUSED_SMEM_FLOATS * (int)sizeof(float));
    cudaFuncSetAttribute(ipe_kernel, cudaFuncAttributeMaxDynamicSharedMemorySize,
                         IPE_SMEM_FLOATS * (int)sizeof(float));

    mask_conv_kernel<<<1, 256>>>(mraw);
    qkv_kernel<<<64, 256>>>(x, Wq, bq, Wk, bk, Wv, bv);
    fused_kernel<<<Bb*Nn, 256, FUSED_SMEM_FLOATS * sizeof(float)>>>(
        edge, dist, vec, Wdk, bdk, Wdu, bdu, out_attn);
    w_kernel<<<Bb*24, 256>>>(Wdih);
    ipe_kernel<<<Bb*Nn, 256, IPE_SMEM_FLOATS * sizeof(float)>>>(
        edge, Wea, bea, out_ipe);
}